// round 3
// baseline (speedup 1.0000x reference)
#include <cuda_runtime.h>

#define BATCH 64
#define SEQ   1024
#define DIM   1280
#define H1    640
#define H2    320

#define LSEG       16         // L-split segments for pooling
#define SEGLEN     (SEQ / LSEG)   // 64
#define DSPLIT     2          // D halved across blocks
#define PTHREADS   160        // pool threads per block (float4 columns per half)
#define KS1        8          // k-splits for GEMM1 (1280/8 = 160)
#define KS2        4          // k-splits for GEMM2 (640/4  = 160)
#define KR         160        // k-range per split (both gemms)
#define JT         32         // output-column tile
#define KT         32         // k chunk staged in smem
#define SP_STRIDE  33         // padded smem stride (bank-conflict free)

// Scratch (partials — written fully every launch, no zeroing, no atomics,
// fully deterministic)
__device__ float g_poolp[LSEG][BATCH * DIM];   // raw masked sums per L-segment
__device__ float g_z1p[KS1][BATCH * H1];       // layer-1 pre-activation partials
__device__ float g_z2p[KS2][BATCH * H2];       // layer-2 pre-activation partials

// ---------------------------------------------------------------------------
// Pool: masked sum of rep[b, 1:len-1, :] into per-segment partials.
// grid (DSPLIT, 64, LSEG), 160 threads; thread owns one float4 column.
// ---------------------------------------------------------------------------
__global__ void pool_kernel(const float* __restrict__ rep,
                            const int* __restrict__ blen) {
    const int b   = blockIdx.y;
    const int seg = blockIdx.z;
    const int hi  = blen[b] - 1;                 // exclusive upper row bound
    int l0 = seg * SEGLEN; if (l0 < 1) l0 = 1;
    int l1 = (seg + 1) * SEGLEN; if (l1 > hi) l1 = hi;

    const int d4 = blockIdx.x * PTHREADS + threadIdx.x;  // float4 col in [0,320)
    float* dst = &g_poolp[seg][b * DIM + d4 * 4];

    if (l0 >= l1) {                               // empty segment: zero + exit
        dst[0] = 0.f; dst[1] = 0.f; dst[2] = 0.f; dst[3] = 0.f;
        return;
    }

    const float4* base =
        reinterpret_cast<const float4*>(rep + (size_t)b * SEQ * DIM) + d4;
    const int row4 = DIM / 4;

    float4 acc = make_float4(0.f, 0.f, 0.f, 0.f);
    int l = l0;
    for (; l + 3 < l1; l += 4) {
        float4 a0 = base[(size_t)(l + 0) * row4];
        float4 a1 = base[(size_t)(l + 1) * row4];
        float4 a2 = base[(size_t)(l + 2) * row4];
        float4 a3 = base[(size_t)(l + 3) * row4];
        acc.x += (a0.x + a1.x) + (a2.x + a3.x);
        acc.y += (a0.y + a1.y) + (a2.y + a3.y);
        acc.z += (a0.z + a1.z) + (a2.z + a3.z);
        acc.w += (a0.w + a1.w) + (a2.w + a3.w);
    }
    for (; l < l1; ++l) {
        float4 a = base[(size_t)l * row4];
        acc.x += a.x; acc.y += a.y; acc.z += a.z; acc.w += a.w;
    }
    dst[0] = acc.x; dst[1] = acc.y; dst[2] = acc.z; dst[3] = acc.w;
}

// ---------------------------------------------------------------------------
// GEMM1: z1 += (pooled/count) @ W1   (partials per k-split)
// grid (20 j-tiles, 8 k-splits), 128 threads.
// Thread: jq = t&7 -> 4 cols, bq = t>>3 -> 4 batches => 4x4 register tile.
// ---------------------------------------------------------------------------
__global__ void gemm1_kernel(const float* __restrict__ W1,
                             const int* __restrict__ blen) {
    __shared__ float sW[KT * JT];
    __shared__ float sP[BATCH * SP_STRIDE];
    __shared__ float rc[BATCH];

    const int t  = threadIdx.x;
    const int j0 = blockIdx.x * JT;
    const int k0 = blockIdx.y * KR;
    const int jq = t & 7;
    const int bq = t >> 3;

    if (t < BATCH) {
        int c = blen[t] - 2; if (c < 1) c = 1;
        rc[t] = 1.0f / (float)c;
    }

    float acc[4][4] = {};

    for (int kc = 0; kc < KR; kc += KT) {
        __syncthreads();
        // stage W1 tile [KT][JT]
#pragma unroll
        for (int r = 0; r < (KT * JT) / 128; ++r) {
            int e  = r * 128 + t;
            int kk = e >> 5, jj = e & 31;
            sW[e] = W1[(size_t)(k0 + kc + kk) * H1 + j0 + jj];
        }
        // stage pooled tile [BATCH][KT]: sum LSEG partials, scale 1/count
#pragma unroll
        for (int r = 0; r < (BATCH * KT) / 128; ++r) {
            int e  = r * 128 + t;
            int b  = e >> 5, kk = e & 31;
            int gi = b * DIM + k0 + kc + kk;
            float s = 0.f;
#pragma unroll
            for (int sg = 0; sg < LSEG; ++sg) s += g_poolp[sg][gi];
            sP[b * SP_STRIDE + kk] = s * rc[b];
        }
        __syncthreads();
#pragma unroll
        for (int kk = 0; kk < KT; ++kk) {
            float4 w = *reinterpret_cast<const float4*>(&sW[kk * JT + jq * 4]);
#pragma unroll
            for (int i = 0; i < 4; ++i) {
                float p = sP[(bq * 4 + i) * SP_STRIDE + kk];
                acc[i][0] += p * w.x; acc[i][1] += p * w.y;
                acc[i][2] += p * w.z; acc[i][3] += p * w.w;
            }
        }
    }

    float* zp = g_z1p[blockIdx.y];
#pragma unroll
    for (int i = 0; i < 4; ++i) {
        int b = bq * 4 + i;
#pragma unroll
        for (int jj = 0; jj < 4; ++jj)
            zp[b * H1 + j0 + jq * 4 + jj] = acc[i][jj];
    }
}

// ---------------------------------------------------------------------------
// GEMM2: z2 += relu(z1 + b1) @ W2   (partials per k-split)
// grid (10 j-tiles, 4 k-splits), 128 threads. Same tiling as GEMM1.
// ---------------------------------------------------------------------------
__global__ void gemm2_kernel(const float* __restrict__ W2,
                             const float* __restrict__ b1) {
    __shared__ float sW[KT * JT];
    __shared__ float sP[BATCH * SP_STRIDE];

    const int t  = threadIdx.x;
    const int j0 = blockIdx.x * JT;
    const int k0 = blockIdx.y * KR;
    const int jq = t & 7;
    const int bq = t >> 3;

    float acc[4][4] = {};

    for (int kc = 0; kc < KR; kc += KT) {
        __syncthreads();
#pragma unroll
        for (int r = 0; r < (KT * JT) / 128; ++r) {
            int e  = r * 128 + t;
            int kk = e >> 5, jj = e & 31;
            sW[e] = W2[(size_t)(k0 + kc + kk) * H2 + j0 + jj];
        }
#pragma unroll
        for (int r = 0; r < (BATCH * KT) / 128; ++r) {
            int e  = r * 128 + t;
            int b  = e >> 5, kk = e & 31;
            int k  = k0 + kc + kk;
            int gi = b * H1 + k;
            float z = 0.f;
#pragma unroll
            for (int s = 0; s < KS1; ++s) z += g_z1p[s][gi];
            z += b1[k];
            sP[b * SP_STRIDE + kk] = fmaxf(z, 0.f);
        }
        __syncthreads();
#pragma unroll
        for (int kk = 0; kk < KT; ++kk) {
            float4 w = *reinterpret_cast<const float4*>(&sW[kk * JT + jq * 4]);
#pragma unroll
            for (int i = 0; i < 4; ++i) {
                float p = sP[(bq * 4 + i) * SP_STRIDE + kk];
                acc[i][0] += p * w.x; acc[i][1] += p * w.y;
                acc[i][2] += p * w.z; acc[i][3] += p * w.w;
            }
        }
    }

    float* zp = g_z2p[blockIdx.y];
#pragma unroll
    for (int i = 0; i < 4; ++i) {
        int b = bq * 4 + i;
#pragma unroll
        for (int jj = 0; jj < 4; ++jj)
            zp[b * H2 + j0 + jq * 4 + jj] = acc[i][jj];
    }
}

// ---------------------------------------------------------------------------
// Final: one block per batch (64 blocks, 320 threads). Thread t owns k=t:
//   emb[b,k] = relu(sum_s z2p[s] + b2[k])  -> out[128 + b*320 + k]
//   y[b,o]   = sum_k emb[b,k]*W3[k,o] + b3 -> out[b*2 + o]  (block reduction)
// ---------------------------------------------------------------------------
__global__ void final_kernel(const float* __restrict__ b2,
                             const float* __restrict__ W3,
                             const float* __restrict__ b3,
                             float* __restrict__ out) {
    const int b = blockIdx.x;
    const int k = threadIdx.x;            // 0..319
    const int gi = b * H2 + k;

    float z = 0.f;
#pragma unroll
    for (int s = 0; s < KS2; ++s) z += g_z2p[s][gi];
    float e = fmaxf(z + b2[k], 0.f);
    out[BATCH * 2 + gi] = e;

    float2 w = *reinterpret_cast<const float2*>(&W3[k * 2]);
    float p0 = e * w.x;
    float p1 = e * w.y;

    // warp reduce
#pragma unroll
    for (int off = 16; off > 0; off >>= 1) {
        p0 += __shfl_down_sync(0xFFFFFFFFu, p0, off);
        p1 += __shfl_down_sync(0xFFFFFFFFu, p1, off);
    }
    __shared__ float s0[10], s1[10];
    const int wid = k >> 5, lid = k & 31;
    if (lid == 0) { s0[wid] = p0; s1[wid] = p1; }
    __syncthreads();
    if (k == 0) {
        float a0 = 0.f, a1 = 0.f;
#pragma unroll
        for (int wi = 0; wi < 10; ++wi) { a0 += s0[wi]; a1 += s1[wi]; }
        out[b * 2 + 0] = a0 + b3[0];
        out[b * 2 + 1] = a1 + b3[1];
    }
}

// ---------------------------------------------------------------------------
extern "C" void kernel_launch(void* const* d_in, const int* in_sizes, int n_in,
                              void* d_out, int out_size) {
    const float* rep  = (const float*)d_in[0];
    const int*   blen = (const int*)  d_in[1];
    const float* W1   = (const float*)d_in[2];
    const float* b1   = (const float*)d_in[3];
    const float* W2   = (const float*)d_in[4];
    const float* b2   = (const float*)d_in[5];
    const float* W3   = (const float*)d_in[6];
    const float* b3   = (const float*)d_in[7];
    float* out = (float*)d_out;

    pool_kernel <<<dim3(DSPLIT, BATCH, LSEG), PTHREADS>>>(rep, blen);
    gemm1_kernel<<<dim3(H1 / JT, KS1), 128>>>(W1, blen);
    gemm2_kernel<<<dim3(H2 / JT, KS2), 128>>>(W2, b1);
    final_kernel<<<BATCH, H2>>>(b2, W3, b3, out);
}

// round 4
// speedup vs baseline: 1.0703x; 1.0703x over previous
#include <cuda_runtime.h>

#define BATCH 64
#define SEQ   1024
#define DIM   1280
#define H1    640
#define H2    320

#define LSEG       16         // round-robin row groups for pooling
#define KS1        8          // k-splits for GEMM1 (1280/8 = 160)
#define KS2        4          // k-splits for GEMM2 (640/4  = 160)
#define KR         160        // k-range per split (both gemms)
#define JT         32         // output-column tile
#define KT         32         // k chunk staged in smem
#define SP_STRIDE  33         // padded smem stride (bank-conflict free)

// Scratch (partials — written fully every launch, no zeroing, no atomics,
// fully deterministic)
__device__ float g_poolp[LSEG][BATCH * DIM];   // raw masked sums per row-group
__device__ float g_z1p[KS1][BATCH * H1];       // layer-1 pre-activation partials
__device__ float g_z2p[KS2][BATCH * H2];       // layer-2 pre-activation partials

// ---------------------------------------------------------------------------
// Pool: masked sum of rep[b, 1:len-1, :] into per-group partials.
// Group s owns rows l with l % LSEG == s  ->  perfect load balance: every
// block of a batch processes ceil(rows/16) +- 1 rows. No empty blocks.
// grid (64, 16), 320 threads; thread owns one float4 column.
// ---------------------------------------------------------------------------
__global__ void pool_kernel(const float* __restrict__ rep,
                            const int* __restrict__ blen) {
    const int b  = blockIdx.x;
    const int s  = blockIdx.y;
    const int hi = blen[b] - 1;                  // exclusive upper row bound

    const int d4 = threadIdx.x;                  // float4 col in [0,320)
    const float4* base =
        reinterpret_cast<const float4*>(rep + (size_t)b * SEQ * DIM) + d4;
    const int row4 = DIM / 4;

    int l = (s == 0) ? LSEG : s;                 // first row >= 1 with l%16==s
    const int STEP = LSEG;

    float4 acc = make_float4(0.f, 0.f, 0.f, 0.f);
    // unroll-4: rows l, l+16, l+32, l+48 — independent loads, MLP=4
    for (; l + 3 * STEP < hi; l += 4 * STEP) {
        float4 a0 = base[(size_t)(l + 0 * STEP) * row4];
        float4 a1 = base[(size_t)(l + 1 * STEP) * row4];
        float4 a2 = base[(size_t)(l + 2 * STEP) * row4];
        float4 a3 = base[(size_t)(l + 3 * STEP) * row4];
        acc.x += (a0.x + a1.x) + (a2.x + a3.x);
        acc.y += (a0.y + a1.y) + (a2.y + a3.y);
        acc.z += (a0.z + a1.z) + (a2.z + a3.z);
        acc.w += (a0.w + a1.w) + (a2.w + a3.w);
    }
    for (; l < hi; l += STEP) {
        float4 a = base[(size_t)l * row4];
        acc.x += a.x; acc.y += a.y; acc.z += a.z; acc.w += a.w;
    }
    float* dst = &g_poolp[s][b * DIM + d4 * 4];
    dst[0] = acc.x; dst[1] = acc.y; dst[2] = acc.z; dst[3] = acc.w;
}

// ---------------------------------------------------------------------------
// GEMM1: z1 += (pooled/count) @ W1   (partials per k-split)
// grid (20 j-tiles, 8 k-splits), 128 threads.
// Thread: jq = t&7 -> 4 cols, bq = t>>3 -> 4 batches => 4x4 register tile.
// ---------------------------------------------------------------------------
__global__ void gemm1_kernel(const float* __restrict__ W1,
                             const int* __restrict__ blen) {
    __shared__ float sW[KT * JT];
    __shared__ float sP[BATCH * SP_STRIDE];
    __shared__ float rc[BATCH];

    const int t  = threadIdx.x;
    const int j0 = blockIdx.x * JT;
    const int k0 = blockIdx.y * KR;
    const int jq = t & 7;
    const int bq = t >> 3;

    if (t < BATCH) {
        int c = blen[t] - 2; if (c < 1) c = 1;
        rc[t] = 1.0f / (float)c;
    }

    float acc[4][4] = {};

    for (int kc = 0; kc < KR; kc += KT) {
        __syncthreads();
        // stage W1 tile [KT][JT]
#pragma unroll
        for (int r = 0; r < (KT * JT) / 128; ++r) {
            int e  = r * 128 + t;
            int kk = e >> 5, jj = e & 31;
            sW[e] = W1[(size_t)(k0 + kc + kk) * H1 + j0 + jj];
        }
        // stage pooled tile [BATCH][KT]: sum LSEG partials, scale 1/count
#pragma unroll
        for (int r = 0; r < (BATCH * KT) / 128; ++r) {
            int e  = r * 128 + t;
            int b  = e >> 5, kk = e & 31;
            int gi = b * DIM + k0 + kc + kk;
            float s = 0.f;
#pragma unroll
            for (int sg = 0; sg < LSEG; ++sg) s += g_poolp[sg][gi];
            sP[b * SP_STRIDE + kk] = s * rc[b];
        }
        __syncthreads();
#pragma unroll
        for (int kk = 0; kk < KT; ++kk) {
            float4 w = *reinterpret_cast<const float4*>(&sW[kk * JT + jq * 4]);
#pragma unroll
            for (int i = 0; i < 4; ++i) {
                float p = sP[(bq * 4 + i) * SP_STRIDE + kk];
                acc[i][0] += p * w.x; acc[i][1] += p * w.y;
                acc[i][2] += p * w.z; acc[i][3] += p * w.w;
            }
        }
    }

    float* zp = g_z1p[blockIdx.y];
#pragma unroll
    for (int i = 0; i < 4; ++i) {
        int b = bq * 4 + i;
#pragma unroll
        for (int jj = 0; jj < 4; ++jj)
            zp[b * H1 + j0 + jq * 4 + jj] = acc[i][jj];
    }
}

// ---------------------------------------------------------------------------
// GEMM2: z2 += relu(z1 + b1) @ W2   (partials per k-split)
// grid (10 j-tiles, 4 k-splits), 128 threads. Same tiling as GEMM1.
// ---------------------------------------------------------------------------
__global__ void gemm2_kernel(const float* __restrict__ W2,
                             const float* __restrict__ b1) {
    __shared__ float sW[KT * JT];
    __shared__ float sP[BATCH * SP_STRIDE];

    const int t  = threadIdx.x;
    const int j0 = blockIdx.x * JT;
    const int k0 = blockIdx.y * KR;
    const int jq = t & 7;
    const int bq = t >> 3;

    float acc[4][4] = {};

    for (int kc = 0; kc < KR; kc += KT) {
        __syncthreads();
#pragma unroll
        for (int r = 0; r < (KT * JT) / 128; ++r) {
            int e  = r * 128 + t;
            int kk = e >> 5, jj = e & 31;
            sW[e] = W2[(size_t)(k0 + kc + kk) * H2 + j0 + jj];
        }
#pragma unroll
        for (int r = 0; r < (BATCH * KT) / 128; ++r) {
            int e  = r * 128 + t;
            int b  = e >> 5, kk = e & 31;
            int k  = k0 + kc + kk;
            int gi = b * H1 + k;
            float z = 0.f;
#pragma unroll
            for (int s = 0; s < KS1; ++s) z += g_z1p[s][gi];
            z += b1[k];
            sP[b * SP_STRIDE + kk] = fmaxf(z, 0.f);
        }
        __syncthreads();
#pragma unroll
        for (int kk = 0; kk < KT; ++kk) {
            float4 w = *reinterpret_cast<const float4*>(&sW[kk * JT + jq * 4]);
#pragma unroll
            for (int i = 0; i < 4; ++i) {
                float p = sP[(bq * 4 + i) * SP_STRIDE + kk];
                acc[i][0] += p * w.x; acc[i][1] += p * w.y;
                acc[i][2] += p * w.z; acc[i][3] += p * w.w;
            }
        }
    }

    float* zp = g_z2p[blockIdx.y];
#pragma unroll
    for (int i = 0; i < 4; ++i) {
        int b = bq * 4 + i;
#pragma unroll
        for (int jj = 0; jj < 4; ++jj)
            zp[b * H2 + j0 + jq * 4 + jj] = acc[i][jj];
    }
}

// ---------------------------------------------------------------------------
// Final: one block per batch (64 blocks, 320 threads). Thread t owns k=t:
//   emb[b,k] = relu(sum_s z2p[s] + b2[k])  -> out[128 + b*320 + k]
//   y[b,o]   = sum_k emb[b,k]*W3[k,o] + b3 -> out[b*2 + o]  (block reduction)
// ---------------------------------------------------------------------------
__global__ void final_kernel(const float* __restrict__ b2,
                             const float* __restrict__ W3,
                             const float* __restrict__ b3,
                             float* __restrict__ out) {
    const int b = blockIdx.x;
    const int k = threadIdx.x;            // 0..319
    const int gi = b * H2 + k;

    float z = 0.f;
#pragma unroll
    for (int s = 0; s < KS2; ++s) z += g_z2p[s][gi];
    float e = fmaxf(z + b2[k], 0.f);
    out[BATCH * 2 + gi] = e;

    float2 w = *reinterpret_cast<const float2*>(&W3[k * 2]);
    float p0 = e * w.x;
    float p1 = e * w.y;

    // warp reduce
#pragma unroll
    for (int off = 16; off > 0; off >>= 1) {
        p0 += __shfl_down_sync(0xFFFFFFFFu, p0, off);
        p1 += __shfl_down_sync(0xFFFFFFFFu, p1, off);
    }
    __shared__ float s0[10], s1[10];
    const int wid = k >> 5, lid = k & 31;
    if (lid == 0) { s0[wid] = p0; s1[wid] = p1; }
    __syncthreads();
    if (k == 0) {
        float a0 = 0.f, a1 = 0.f;
#pragma unroll
        for (int wi = 0; wi < 10; ++wi) { a0 += s0[wi]; a1 += s1[wi]; }
        out[b * 2 + 0] = a0 + b3[0];
        out[b * 2 + 1] = a1 + b3[1];
    }
}

// ---------------------------------------------------------------------------
extern "C" void kernel_launch(void* const* d_in, const int* in_sizes, int n_in,
                              void* d_out, int out_size) {
    const float* rep  = (const float*)d_in[0];
    const int*   blen = (const int*)  d_in[1];
    const float* W1   = (const float*)d_in[2];
    const float* b1   = (const float*)d_in[3];
    const float* W2   = (const float*)d_in[4];
    const float* b2   = (const float*)d_in[5];
    const float* W3   = (const float*)d_in[6];
    const float* b3   = (const float*)d_in[7];
    float* out = (float*)d_out;

    pool_kernel <<<dim3(BATCH, LSEG), 320>>>(rep, blen);
    gemm1_kernel<<<dim3(H1 / JT, KS1), 128>>>(W1, blen);
    gemm2_kernel<<<dim3(H2 / JT, KS2), 128>>>(W2, b1);
    final_kernel<<<BATCH, H2>>>(b2, W3, b3, out);
}

// round 5
// speedup vs baseline: 1.5773x; 1.4737x over previous
#include <cuda_runtime.h>

#define BATCH 64
#define SEQ   1024
#define DIM   1280
#define H1    640
#define H2    320

#define GSEG       8          // proportional contiguous row-groups per batch
#define KS1        8          // k-splits for GEMM1 (1280/8 = 160)
#define KS2        4          // k-splits for GEMM2 (640/4  = 160)
#define KR         160        // k-range per split (both gemms)
#define JT         32         // output-column tile
#define KT         32         // k chunk staged in smem
#define SP_STRIDE  33         // padded smem stride (bank-conflict free)

// Scratch (partials — written fully every launch, no zeroing, no atomics,
// fully deterministic)
__device__ float g_poolp[GSEG][BATCH * DIM];   // raw masked sums per row-group
__device__ float g_z1p[KS1][BATCH * H1];       // layer-1 pre-activation partials
__device__ float g_z2p[KS2][BATCH * H2];       // layer-2 pre-activation partials

// ---------------------------------------------------------------------------
// Pool: masked sum of rep[b, 1:len-1, :] into per-group partials.
// Group g owns the CONTIGUOUS row range [1 + n*g/8, 1 + n*(g+1)/8), n=len-2.
// -> every block busy, equal within-batch work, contiguous DRAM streaming.
// grid (64, 8), 320 threads; thread owns one float4 column.
// ---------------------------------------------------------------------------
__global__ void pool_kernel(const float* __restrict__ rep,
                            const int* __restrict__ blen) {
    const int b = blockIdx.x;
    const int g = blockIdx.y;
    const int n = blen[b] - 2;                   // rows in [1, len-1)
    const int l0 = 1 + (n * g) / GSEG;
    const int l1 = 1 + (n * (g + 1)) / GSEG;

    const int d4 = threadIdx.x;                  // float4 col in [0,320)
    const float4* base =
        reinterpret_cast<const float4*>(rep + (size_t)b * SEQ * DIM) + d4;
    const int row4 = DIM / 4;

    float4 acc = make_float4(0.f, 0.f, 0.f, 0.f);
    int l = l0;
    // unroll-8: 8 independent loads in flight per thread
    for (; l + 7 < l1; l += 8) {
        float4 a0 = base[(size_t)(l + 0) * row4];
        float4 a1 = base[(size_t)(l + 1) * row4];
        float4 a2 = base[(size_t)(l + 2) * row4];
        float4 a3 = base[(size_t)(l + 3) * row4];
        float4 a4 = base[(size_t)(l + 4) * row4];
        float4 a5 = base[(size_t)(l + 5) * row4];
        float4 a6 = base[(size_t)(l + 6) * row4];
        float4 a7 = base[(size_t)(l + 7) * row4];
        acc.x += ((a0.x + a1.x) + (a2.x + a3.x)) + ((a4.x + a5.x) + (a6.x + a7.x));
        acc.y += ((a0.y + a1.y) + (a2.y + a3.y)) + ((a4.y + a5.y) + (a6.y + a7.y));
        acc.z += ((a0.z + a1.z) + (a2.z + a3.z)) + ((a4.z + a5.z) + (a6.z + a7.z));
        acc.w += ((a0.w + a1.w) + (a2.w + a3.w)) + ((a4.w + a5.w) + (a6.w + a7.w));
    }
    for (; l < l1; ++l) {
        float4 a = base[(size_t)l * row4];
        acc.x += a.x; acc.y += a.y; acc.z += a.z; acc.w += a.w;
    }
    float* dst = &g_poolp[g][b * DIM + d4 * 4];
    dst[0] = acc.x; dst[1] = acc.y; dst[2] = acc.z; dst[3] = acc.w;
}

// ---------------------------------------------------------------------------
// GEMM1: z1 += (pooled/count) @ W1   (partials per k-split)
// grid (20 j-tiles, 8 k-splits), 128 threads.
// Thread: jq = t&7 -> 4 cols, bq = t>>3 -> 4 batches => 4x4 register tile.
// ---------------------------------------------------------------------------
__global__ void gemm1_kernel(const float* __restrict__ W1,
                             const int* __restrict__ blen) {
    __shared__ float sW[KT * JT];
    __shared__ float sP[BATCH * SP_STRIDE];
    __shared__ float rc[BATCH];

    const int t  = threadIdx.x;
    const int j0 = blockIdx.x * JT;
    const int k0 = blockIdx.y * KR;
    const int jq = t & 7;
    const int bq = t >> 3;

    if (t < BATCH) {
        int c = blen[t] - 2; if (c < 1) c = 1;
        rc[t] = 1.0f / (float)c;
    }

    float acc[4][4] = {};

    for (int kc = 0; kc < KR; kc += KT) {
        __syncthreads();
        // stage W1 tile [KT][JT]
#pragma unroll
        for (int r = 0; r < (KT * JT) / 128; ++r) {
            int e  = r * 128 + t;
            int kk = e >> 5, jj = e & 31;
            sW[e] = W1[(size_t)(k0 + kc + kk) * H1 + j0 + jj];
        }
        // stage pooled tile [BATCH][KT]: sum GSEG partials, scale 1/count
#pragma unroll
        for (int r = 0; r < (BATCH * KT) / 128; ++r) {
            int e  = r * 128 + t;
            int b  = e >> 5, kk = e & 31;
            int gi = b * DIM + k0 + kc + kk;
            float s = 0.f;
#pragma unroll
            for (int sg = 0; sg < GSEG; ++sg) s += g_poolp[sg][gi];
            sP[b * SP_STRIDE + kk] = s * rc[b];
        }
        __syncthreads();
#pragma unroll
        for (int kk = 0; kk < KT; ++kk) {
            float4 w = *reinterpret_cast<const float4*>(&sW[kk * JT + jq * 4]);
#pragma unroll
            for (int i = 0; i < 4; ++i) {
                float p = sP[(bq * 4 + i) * SP_STRIDE + kk];
                acc[i][0] += p * w.x; acc[i][1] += p * w.y;
                acc[i][2] += p * w.z; acc[i][3] += p * w.w;
            }
        }
    }

    float* zp = g_z1p[blockIdx.y];
#pragma unroll
    for (int i = 0; i < 4; ++i) {
        int b = bq * 4 + i;
#pragma unroll
        for (int jj = 0; jj < 4; ++jj)
            zp[b * H1 + j0 + jq * 4 + jj] = acc[i][jj];
    }
}

// ---------------------------------------------------------------------------
// GEMM2: z2 += relu(z1 + b1) @ W2   (partials per k-split)
// grid (10 j-tiles, 4 k-splits), 128 threads. Same tiling as GEMM1.
// ---------------------------------------------------------------------------
__global__ void gemm2_kernel(const float* __restrict__ W2,
                             const float* __restrict__ b1) {
    __shared__ float sW[KT * JT];
    __shared__ float sP[BATCH * SP_STRIDE];

    const int t  = threadIdx.x;
    const int j0 = blockIdx.x * JT;
    const int k0 = blockIdx.y * KR;
    const int jq = t & 7;
    const int bq = t >> 3;

    float acc[4][4] = {};

    for (int kc = 0; kc < KR; kc += KT) {
        __syncthreads();
#pragma unroll
        for (int r = 0; r < (KT * JT) / 128; ++r) {
            int e  = r * 128 + t;
            int kk = e >> 5, jj = e & 31;
            sW[e] = W2[(size_t)(k0 + kc + kk) * H2 + j0 + jj];
        }
#pragma unroll
        for (int r = 0; r < (BATCH * KT) / 128; ++r) {
            int e  = r * 128 + t;
            int b  = e >> 5, kk = e & 31;
            int k  = k0 + kc + kk;
            int gi = b * H1 + k;
            float z = 0.f;
#pragma unroll
            for (int s = 0; s < KS1; ++s) z += g_z1p[s][gi];
            z += b1[k];
            sP[b * SP_STRIDE + kk] = fmaxf(z, 0.f);
        }
        __syncthreads();
#pragma unroll
        for (int kk = 0; kk < KT; ++kk) {
            float4 w = *reinterpret_cast<const float4*>(&sW[kk * JT + jq * 4]);
#pragma unroll
            for (int i = 0; i < 4; ++i) {
                float p = sP[(bq * 4 + i) * SP_STRIDE + kk];
                acc[i][0] += p * w.x; acc[i][1] += p * w.y;
                acc[i][2] += p * w.z; acc[i][3] += p * w.w;
            }
        }
    }

    float* zp = g_z2p[blockIdx.y];
#pragma unroll
    for (int i = 0; i < 4; ++i) {
        int b = bq * 4 + i;
#pragma unroll
        for (int jj = 0; jj < 4; ++jj)
            zp[b * H2 + j0 + jq * 4 + jj] = acc[i][jj];
    }
}

// ---------------------------------------------------------------------------
// Final: one block per batch (64 blocks, 320 threads). Thread t owns k=t:
//   emb[b,k] = relu(sum_s z2p[s] + b2[k])  -> out[128 + b*320 + k]
//   y[b,o]   = sum_k emb[b,k]*W3[k,o] + b3 -> out[b*2 + o]  (block reduction)
// ---------------------------------------------------------------------------
__global__ void final_kernel(const float* __restrict__ b2,
                             const float* __restrict__ W3,
                             const float* __restrict__ b3,
                             float* __restrict__ out) {
    const int b = blockIdx.x;
    const int k = threadIdx.x;            // 0..319
    const int gi = b * H2 + k;

    float z = 0.f;
#pragma unroll
    for (int s = 0; s < KS2; ++s) z += g_z2p[s][gi];
    float e = fmaxf(z + b2[k], 0.f);
    out[BATCH * 2 + gi] = e;

    float2 w = *reinterpret_cast<const float2*>(&W3[k * 2]);
    float p0 = e * w.x;
    float p1 = e * w.y;

    // warp reduce
#pragma unroll
    for (int off = 16; off > 0; off >>= 1) {
        p0 += __shfl_down_sync(0xFFFFFFFFu, p0, off);
        p1 += __shfl_down_sync(0xFFFFFFFFu, p1, off);
    }
    __shared__ float s0[10], s1[10];
    const int wid = k >> 5, lid = k & 31;
    if (lid == 0) { s0[wid] = p0; s1[wid] = p1; }
    __syncthreads();
    if (k == 0) {
        float a0 = 0.f, a1 = 0.f;
#pragma unroll
        for (int wi = 0; wi < 10; ++wi) { a0 += s0[wi]; a1 += s1[wi]; }
        out[b * 2 + 0] = a0 + b3[0];
        out[b * 2 + 1] = a1 + b3[1];
    }
}

// ---------------------------------------------------------------------------
extern "C" void kernel_launch(void* const* d_in, const int* in_sizes, int n_in,
                              void* d_out, int out_size) {
    const float* rep  = (const float*)d_in[0];
    const int*   blen = (const int*)  d_in[1];
    const float* W1   = (const float*)d_in[2];
    const float* b1   = (const float*)d_in[3];
    const float* W2   = (const float*)d_in[4];
    const float* b2   = (const float*)d_in[5];
    const float* W3   = (const float*)d_in[6];
    const float* b3   = (const float*)d_in[7];
    float* out = (float*)d_out;

    pool_kernel <<<dim3(BATCH, GSEG), 320>>>(rep, blen);
    gemm1_kernel<<<dim3(H1 / JT, KS1), 128>>>(W1, blen);
    gemm2_kernel<<<dim3(H2 / JT, KS2), 128>>>(W2, b1);
    final_kernel<<<BATCH, H2>>>(b2, W3, b3, out);
}